// round 2
// baseline (speedup 1.0000x reference)
#include <cuda_runtime.h>

// WindowWarp: out[b,t,c] = lerp_u( lerp_s(x) )
// B=256, T=2048, C=64, WARP_SIZE=205, L_MAX=2253
// R2: ILP=2 t-rows/thread (8 front-batched LDG.128), weight-form combine,
//     reciprocal for window slope, streaming stores.

#define BB 256
#define TT 2048
#define CC 64
#define ROWF4 (CC / 4)

struct TPos {
    int   i[4];
    float w[4];
};

__device__ __forceinline__ TPos compute_pos(float t, float start, float nl,
                                            float Lm1, float wend, float r204) {
    // outer resample position (exact division to match reference rounding)
    float u = t * Lm1 / 2047.0f;
    u = fminf(u, Lm1);
    float j0 = floorf(u);
    float fu = u - j0;
    float j1 = fminf(j0 + 1.0f, 2252.0f);

    TPos p;
    float jj[2] = {j0, j1};
#pragma unroll
    for (int q = 0; q < 2; q++) {
        float j = jj[q];
        // inner warp map j -> s (branchless selects)
        float s_win = fmaf(j - start, r204, start);
        float s_aft = j - nl + 205.0f;
        float s = j;
        if (j >= start) s = s_win;
        if (j >= wend)  s = s_aft;
        s = fminf(fmaxf(s, 0.0f), 2047.0f);

        float p0 = floorf(s);
        float fr = s - p0;
        int i0 = (int)p0;
        p.i[2 * q]     = i0;
        p.i[2 * q + 1] = min(i0 + 1, TT - 1);
        float wu = q ? fu : (1.0f - fu);
        p.w[2 * q]     = wu * (1.0f - fr);
        p.w[2 * q + 1] = wu * fr;
    }
    return p;
}

__device__ __forceinline__ float4 combine4(const float4* g, const float* w) {
    float4 r;
    r.x = g[0].x * w[0]; r.y = g[0].y * w[0];
    r.z = g[0].z * w[0]; r.w = g[0].w * w[0];
#pragma unroll
    for (int k = 1; k < 4; k++) {
        r.x = fmaf(g[k].x, w[k], r.x);
        r.y = fmaf(g[k].y, w[k], r.y);
        r.z = fmaf(g[k].z, w[k], r.z);
        r.w = fmaf(g[k].w, w[k], r.w);
    }
    return r;
}

__global__ void __launch_bounds__(256) window_warp_kernel(
    const float* __restrict__ x,
    const float* __restrict__ warp_scales,
    const int*   __restrict__ window_starts,
    float* __restrict__ out)
{
    int b    = blockIdx.y;
    int lane = threadIdx.x;                       // 0..15, 4 channels each
    int tA   = blockIdx.x * 32 + threadIdx.y;     // first t row
    int tB   = tA + 16;                           // second t row

    float scale = __ldg(warp_scales + b);
    float start = (float)__ldg(window_starts + b);
    float nl    = floorf(205.0f * scale);
    float Lm1   = (2048.0f - 205.0f + nl) - 1.0f;
    float wend  = start + nl;
    float r204  = 204.0f / fmaxf(nl - 1.0f, 1.0f);   // one division per thread

    TPos pa = compute_pos((float)tA, start, nl, Lm1, wend, r204);
    TPos pb = compute_pos((float)tB, start, nl, Lm1, wend, r204);

    const float4* xb = reinterpret_cast<const float4*>(x + (size_t)b * TT * CC) + lane;

    // front-batch all 8 independent gathers for max MLP
    float4 g[8];
#pragma unroll
    for (int k = 0; k < 4; k++) g[k]     = __ldg(&xb[pa.i[k] * ROWF4]);
#pragma unroll
    for (int k = 0; k < 4; k++) g[4 + k] = __ldg(&xb[pb.i[k] * ROWF4]);

    float4 rA = combine4(g,     pa.w);
    float4 rB = combine4(g + 4, pb.w);

    float4* ob = reinterpret_cast<float4*>(out + (size_t)b * TT * CC) + lane;
    __stcs(&ob[tA * ROWF4], rA);
    __stcs(&ob[tB * ROWF4], rB);
}

extern "C" void kernel_launch(void* const* d_in, const int* in_sizes, int n_in,
                              void* d_out, int out_size) {
    const float* x      = (const float*)d_in[0];
    const float* scales = (const float*)d_in[1];
    const int*   starts = (const int*)d_in[2];
    float* out = (float*)d_out;

    dim3 block(16, 16);          // 16 float4 lanes x 16 (t pairs) = 256 threads
    dim3 grid(TT / 32, BB);      // (64, 256)
    window_warp_kernel<<<grid, block>>>(x, scales, starts, out);
}